// round 8
// baseline (speedup 1.0000x reference)
#include <cuda_runtime.h>
#include <cuda_bf16.h>

// Shapes (fixed by the problem):
//   se_pred: [64, 6]  float32   (384 elems)
//   target : [64, 512, 512] labels 0..5, int32 on device (16777216 elems)
//   out    : scalar float32 mean BCE loss
#define NBATCH   64
#define NCLASS   6
#define PIX      (512 * 512)     // 262144 labels per batch
#define LPB      8               // lanes per batch
#define THREADS  (NBATCH * LPB)  // 512
#define MAX_IT   (PIX / 4 / LPB) // 8192 rounds = full coverage fallback

__global__ void __launch_bounds__(THREADS)
se_one_block_kernel(const int* __restrict__ target,
                    const float* __restrict__ se_pred,
                    float* __restrict__ out) {
    const int tid   = threadIdx.x;
    const int lane  = tid & 31;
    const int batch = tid >> 3;            // 64 groups of 8 lanes
    const int sub   = tid & 7;             // lane within group
    const unsigned hm = 0xFFu << (lane & ~7);   // this group's 8-lane mask

    // Prefetch this lane's prediction NOW so its LDG overlaps the target
    // DRAM latency (lanes 0..5 of each group own the 6 classes).
    float p = 1.0f;
    if (sub < NCLASS) p = se_pred[batch * NCLASS + sub];

    const int4* __restrict__ base = (const int4*)(target + (size_t)batch * PIX);

    // First round: FOUR independent 16B loads per lane (MLP=4) -> 128 labels
    // unioned per 8-lane group. P(any class missing) ~ 6*(5/6)^128 ~ 4e-10,
    // so the fallback loop is statically present but essentially never runs.
    int4 v0 = base[sub];
    int4 v1 = base[LPB + sub];
    int4 v2 = base[2 * LPB + sub];
    int4 v3 = base[3 * LPB + sub];
    int mask = (1 << v0.x) | (1 << v0.y) | (1 << v0.z) | (1 << v0.w)
             | (1 << v1.x) | (1 << v1.y) | (1 << v1.z) | (1 << v1.w)
             | (1 << v2.x) | (1 << v2.y) | (1 << v2.z) | (1 << v2.w)
             | (1 << v3.x) | (1 << v3.y) | (1 << v3.z) | (1 << v3.w);
    mask = __reduce_or_sync(hm, mask);     // uniform within the 8-lane group

    if (mask != 0x3F) {                    // cold path: full-coverage scan
        #pragma unroll 1
        for (int i = 4; i < MAX_IT; ++i) {
            int4 v = base[i * LPB + sub];
            mask |= (1 << v.x) | (1 << v.y) | (1 << v.z) | (1 << v.w);
            mask = __reduce_or_sync(hm, mask);
            if (mask == 0x3F) break;
        }
    }

    // Per-lane BCE term (lanes 0..5 of each group), group butterfly reduce.
    float s = 0.0f;
    if (sub < NCLASS) {
        const float t   = (float)((mask >> sub) & 1);
        // torch BCELoss clamps log at -100; MUFU log is plenty accurate for
        // p in [1e-4, 1-1e-4] (rel err ~1e-5 << 1e-3 threshold).
        const float lp  = fmaxf(__logf(p),        -100.0f);
        const float l1p = fmaxf(__logf(1.0f - p), -100.0f);
        s = -(t * lp + (1.0f - t) * l1p);
    }
    #pragma unroll
    for (int o = 4; o > 0; o >>= 1)
        s += __shfl_xor_sync(hm, s, o);    // offsets 1,2,4 stay in the group

    __shared__ float part[NBATCH];
    if (sub == 0) part[batch] = s;
    __syncthreads();

    // Warp 0 sums the 64 batch partials.
    if (tid < 32) {
        float v = part[tid] + part[tid + 32];
        #pragma unroll
        for (int o = 16; o > 0; o >>= 1)
            v += __shfl_xor_sync(0xFFFFFFFFu, v, o);
        if (tid == 0) out[0] = v * (1.0f / (NBATCH * NCLASS));
    }
}

extern "C" void kernel_launch(void* const* d_in, const int* in_sizes, int n_in,
                              void* d_out, int out_size) {
    // Robust to input ordering: identify by element count.
    const float* se_pred;
    const int*   target;
    if (in_sizes[0] == NBATCH * NCLASS) {
        se_pred = (const float*)d_in[0];
        target  = (const int*)d_in[1];
    } else {
        se_pred = (const float*)d_in[1];
        target  = (const int*)d_in[0];
    }
    float* out = (float*)d_out;

    se_one_block_kernel<<<1, THREADS>>>(target, se_pred, out);
}

// round 9
// speedup vs baseline: 1.0667x; 1.0667x over previous
#include <cuda_runtime.h>
#include <cuda_bf16.h>

// Shapes (fixed by the problem):
//   se_pred: [64, 6]  float32   (384 elems)
//   target : [64, 512, 512] labels 0..5, int32 on device (16777216 elems)
//   out    : scalar float32 mean BCE loss
//
// Strategy: class-presence via sampling with provable fallback. Each batch is
// owned by one half-warp; its first round unions 128 random labels
// (P(missing a present class) ~ 6*(5/6)^128 ~ 4e-10), with a full-coverage
// scan as the cold path. One CTA, one barrier, no global sync, no atomics.
#define NBATCH   64
#define NCLASS   6
#define PIX      (512 * 512)     // 262144 labels per batch
#define THREADS  1024            // one half-warp (16 threads) per batch
#define MAX_IT   (PIX / 4 / 16)  // 4096 rounds = full coverage fallback

__global__ void __launch_bounds__(THREADS)
se_one_block_kernel(const int* __restrict__ target,
                    const float* __restrict__ se_pred,
                    float* __restrict__ out) {
    const int tid   = threadIdx.x;
    const int lane  = tid & 31;
    const int batch = tid >> 4;          // 64 half-warps -> 64 batches
    const int sub   = tid & 15;          // lane within half-warp
    const unsigned hm = (lane < 16) ? 0x0000FFFFu : 0xFFFF0000u;

    // Prefetch this lane's prediction NOW so its LDG overlaps the target
    // DRAM latency (lanes 0..5 of each half-warp own the 6 classes).
    float p = 1.0f;
    if (sub < NCLASS) p = se_pred[batch * NCLASS + sub];

    const int4* __restrict__ base = (const int4*)(target + (size_t)batch * PIX);

    // First round: TWO independent 16B loads per lane -> 128 labels unioned
    // per half-warp. The fallback loop below is statically present but
    // essentially never runs.
    int4 v0 = base[sub];
    int4 v1 = base[16 + sub];
    int mask = (1 << v0.x) | (1 << v0.y) | (1 << v0.z) | (1 << v0.w)
             | (1 << v1.x) | (1 << v1.y) | (1 << v1.z) | (1 << v1.w);
    mask = __reduce_or_sync(hm, mask);       // uniform within half-warp

    if (mask != 0x3F) {                       // cold path: full-coverage scan
        #pragma unroll 1
        for (int i = 2; i < MAX_IT; ++i) {
            int4 v = base[i * 16 + sub];
            mask |= (1 << v.x) | (1 << v.y) | (1 << v.z) | (1 << v.w);
            mask = __reduce_or_sync(hm, mask);
            if (mask == 0x3F) break;
        }
    }

    // Per-lane BCE term (lanes 0..5), then half-warp butterfly reduce.
    float s = 0.0f;
    if (sub < NCLASS) {
        const float t   = (float)((mask >> sub) & 1);
        // torch BCELoss clamps log at -100; MUFU-based fast log is plenty
        // accurate for p in [1e-4, 1-1e-4] (measured rel_err ~1e-7).
        const float lp  = fmaxf(__logf(p),        -100.0f);
        const float l1p = fmaxf(__logf(1.0f - p), -100.0f);
        s = -(t * lp + (1.0f - t) * l1p);
    }
    #pragma unroll
    for (int o = 8; o > 0; o >>= 1)
        s += __shfl_xor_sync(hm, s, o);      // offsets 1,2,4,8 stay in half-warp

    __shared__ float part[NBATCH];
    if (sub == 0) part[batch] = s;
    __syncthreads();

    // Warp 0 sums the 64 batch partials.
    if (tid < 32) {
        float v = part[tid] + part[tid + 32];
        #pragma unroll
        for (int o = 16; o > 0; o >>= 1)
            v += __shfl_xor_sync(0xFFFFFFFFu, v, o);
        if (tid == 0) out[0] = v * (1.0f / (NBATCH * NCLASS));
    }
}

extern "C" void kernel_launch(void* const* d_in, const int* in_sizes, int n_in,
                              void* d_out, int out_size) {
    // Robust to input ordering: identify by element count.
    const float* se_pred;
    const int*   target;
    if (in_sizes[0] == NBATCH * NCLASS) {
        se_pred = (const float*)d_in[0];
        target  = (const int*)d_in[1];
    } else {
        se_pred = (const float*)d_in[1];
        target  = (const int*)d_in[0];
    }
    float* out = (float*)d_out;

    se_one_block_kernel<<<1, THREADS>>>(target, se_pred, out);
}